// round 14
// baseline (speedup 1.0000x reference)
#include <cuda_runtime.h>
#include <math.h>

#define T      4096
#define P      8
#define DM     256
#define DF     4096
#define DK     1024
#define NE     9
#define NBLK   296
#define NTHR   512

#define FREQC  ((float)(9.210340371976184 / 2048.0))

// ---------------- scratch --------------------------------------------------
__device__ float    g_q[DK];
__device__ float    g_u[DF];
__device__ float    g_wtab[144];
__device__ float    g_pc[DF];
__device__ float    g_ov[DK];
__device__ float    g_oacc[DK];
__device__ float    g_Z;
__device__ unsigned g_bar;          // monotonic, never reset

// leader-only-fence grid barrier, monotonic counter, pure spin
__device__ __forceinline__ void gridbar() {
    __syncthreads();
    if (threadIdx.x == 0) {
        asm volatile("fence.acq_rel.gpu;" ::: "memory");
        unsigned my = atomicAdd(&g_bar, 1u) + 1u;
        unsigned target = ((my + NBLK - 1u) / NBLK) * NBLK;
        unsigned cur;
        for (;;) {
            asm volatile("ld.acquire.gpu.u32 %0, [%1];" : "=r"(cur) : "l"(&g_bar) : "memory");
            if ((int)(cur - target) >= 0) break;
        }
    }
    __syncthreads();
}

// per-freq seed: theta = exp(-j*FREQC) < 1 rad -> fast-path sincos
__device__ __forceinline__ void freq_seed(int j, float& s1, float& c1) {
    float fij = __expf(-(float)j * FREQC);
    __sincosf(fij, &s1, &c1);
}

// scalar rotpow (branch-free select), B bits: sincos(n*theta) from sincos(theta)
template <int B>
__device__ __forceinline__ void rotpow_s(float ps, float pc, unsigned n,
                                         float& so, float& co) {
    float s = 0.f, c = 1.f;
#pragma unroll
    for (int b = 0; b < B; b++) {
        float ns = fmaf(s, pc, c * ps);
        float nc = fmaf(c, pc, -s * ps);
        bool tk = (n >> b) & 1u;
        s = tk ? ns : s; c = tk ? nc : c;
        float t2 = 2.f * ps * pc;
        pc = fmaf(pc, pc, -ps * ps);
        ps = t2;
    }
    so = s; co = c;
}

// colmv: y[k] += sum_d shx[d]*W[d,k]; two 256-thread halves as vCTAs,
// 4-row chunks, double-buffered
__device__ __forceinline__ void colmv_sh(const float* __restrict__ W,
                                         const float* shx,
                                         float* __restrict__ y, int nvb,
                                         float* sh_acc) {
    int tid = threadIdx.x;
    int htid = tid & 255, half = tid >> 8;
    const float4* W4 = (const float4*)W;
    float4 acc = make_float4(0.f, 0.f, 0.f, 0.f);
    int vb = blockIdx.x * 2 + half;       // 0..591
    if (vb < nvb) {
        float4 w[4]; float xv[4];
#pragma unroll
        for (int i = 0; i < 4; i++) w[i] = __ldg(&W4[(size_t)(vb * 4 + i) * 256 + htid]);
#pragma unroll
        for (int i = 0; i < 4; i++) xv[i] = shx[vb * 4 + i];
        for (int nxt = vb + 2 * NBLK; ; nxt += 2 * NBLK) {
            float4 w2[4]; float xv2[4];
            bool more = nxt < nvb;
            if (more) {
#pragma unroll
                for (int i = 0; i < 4; i++) w2[i] = __ldg(&W4[(size_t)(nxt * 4 + i) * 256 + htid]);
#pragma unroll
                for (int i = 0; i < 4; i++) xv2[i] = shx[nxt * 4 + i];
            }
#pragma unroll
            for (int i = 0; i < 4; i++) {
                acc.x = fmaf(xv[i], w[i].x, acc.x);
                acc.y = fmaf(xv[i], w[i].y, acc.y);
                acc.z = fmaf(xv[i], w[i].z, acc.z);
                acc.w = fmaf(xv[i], w[i].w, acc.w);
            }
            if (!more) break;
#pragma unroll
            for (int i = 0; i < 4; i++) { w[i] = w2[i]; xv[i] = xv2[i]; }
        }
    }
    if (half == 1) ((float4*)sh_acc)[htid] = acc;
    __syncthreads();
    if (half == 0) {
        float4 o = ((float4*)sh_acc)[htid];
        atomicAdd(&y[4 * htid + 0], acc.x + o.x);
        atomicAdd(&y[4 * htid + 1], acc.y + o.y);
        atomicAdd(&y[4 * htid + 2], acc.z + o.z);
        atomicAdd(&y[4 * htid + 3], acc.w + o.w);
    }
}

// ---------------- pre kernel: zeros only ------------------------------------
__global__ void pre_kernel() {
    int g = blockIdx.x * blockDim.x + threadIdx.x;   // 4096 threads
    if (g < DF) g_pc[g] = 0.f;
    if (g < DK) { g_q[g] = 0.f; g_ov[g] = 0.f; g_oacc[g] = 0.f; }
    if (g < 144) g_wtab[g] = 0.f;
    if (g == 0) g_Z = 0.f;
}

// ---------------- uber kernel ----------------------------------------------
__global__ void __launch_bounds__(NTHR, 2)
uber_kernel(const int* __restrict__ obs,
            const float* __restrict__ oe, const float* __restrict__ de,
            const float* __restrict__ WQ, const float* __restrict__ WK,
            const float* __restrict__ WV, const float* __restrict__ WO,
            const float* __restrict__ Wo, const float* __restrict__ bo,
            const float* __restrict__ Wd, const float* __restrict__ bd,
            const float* __restrict__ Wv, const float* __restrict__ bv,
            float* __restrict__ out, int out_size) {
    __shared__ float sbuf[7168];        // 28KB: [x 4096 | acc 1024] or sh_part[14][512]
    __shared__ float sh_tab[144];       // utab
    __shared__ float sh_wt[144];        // block wtab
    __shared__ float sh_e[16];
    __shared__ float sh_red[16];
    __shared__ int   sh_io[112], sh_id[112];

    float* sh_x    = sbuf;
    float* sh_acc  = sbuf + 4096;
    float* sh_part = sbuf;

    int tid = threadIdx.x, bid = blockIdx.x;
    int wid = tid >> 5, lane = tid & 31;

    // ===== P1: build xlast in smem; q = xlast @ WQ ==========================
    for (int k = tid; k < DF; k += NTHR) {
        int d = k, p = d >> 9, r = d & 511;
        int row = 2 * ((T - 1) * P + p) + (r >= DM ? 1 : 0);
        const int* ro = obs + (size_t)row * NE;
        int idx = 0;
#pragma unroll
        for (int e = 0; e < NE; e++) if (ro[e]) idx = e;
        float ev = (r < DM) ? oe[idx * DM + r] : de[idx * DM + (r - DM)];
        float s1, c1; freq_seed(d >> 1, s1, c1);
        float s, c;
        rotpow_s<12>(s1, c1, T - 1, s, c);
        sh_x[k] = 16.0f * ev + ((d & 1) ? c : s);
    }
    __syncthreads();
    colmv_sh(WQ, sh_x, g_q, 1024, sh_acc);
    gridbar();

    // ===== P2: u = WK @ q  (one 16-row vb per block) =======================
    if (tid < 256) ((float4*)sbuf)[tid] = ((const float4*)g_q)[tid];
    __syncthreads();
    if (bid < 256) {
        const float4* Wr = (const float4*)(WK + (size_t)(bid * 16 + wid) * DK);
        float4 w[8];
#pragma unroll
        for (int i = 0; i < 8; i++) w[i] = __ldg(&Wr[lane + 32 * i]);
        float acc = 0.f;
#pragma unroll
        for (int i = 0; i < 8; i++) {
            float4 v = ((float4*)sbuf)[lane + 32 * i];
            acc = fmaf(w[i].x, v.x, acc);
            acc = fmaf(w[i].y, v.y, acc);
            acc = fmaf(w[i].z, v.z, acc);
            acc = fmaf(w[i].w, v.w, acc);
        }
#pragma unroll
        for (int o = 16; o; o >>= 1) acc += __shfl_xor_sync(0xffffffffu, acc, o);
        if (!lane) g_u[bid * 16 + wid] = acc;
    }
    gridbar();

    // ===== P34: fused scores + e + wtab + Z + pc (14 t per block) ==========
    {
        int t0 = bid * 14;
        int nt = min(14, T - t0);
        if (nt > 0) {
            // local io/id decode for this block's 14 x 8 (t,p) pairs
            if (tid < nt * 8) {
                int tt = tid >> 3, p = tid & 7;
                int t = t0 + tt;
                const int* r0 = obs + (size_t)(2 * (t * P + p)) * NE;
                int io = 0, id = 0;
#pragma unroll
                for (int e = 0; e < NE; e++) {
                    if (r0[e])      io = e;
                    if (r0[NE + e]) id = e;
                }
                sh_io[tid] = io;
                sh_id[tid] = id;
            }
            // utab: 144 emb-dot entries vs u (16 warps)
            for (int ent = wid; ent < 144; ent += 16) {
                int kind = ent / 72, p = (ent % 72) / 9, e = ent % 9;
                const float4* e4 = (const float4*)((kind ? de : oe) + e * DM);
                const float4* u4 = (const float4*)(g_u + p * 512 + kind * DM);
                float acc = 0.f;
#pragma unroll
                for (int i = 0; i < 2; i++) {
                    float4 a = __ldg(&e4[lane + 32 * i]);
                    float4 b = u4[lane + 32 * i];
                    acc += a.x * b.x + a.y * b.y + a.z * b.z + a.w * b.w;
                }
#pragma unroll
                for (int o = 16; o; o >>= 1) acc += __shfl_xor_sync(0xffffffffu, acc, o);
                if (!lane) sh_tab[ent] = acc;
            }
            if (tid < 144) sh_wt[tid] = 0.f;

            // seeds: thread owns jp = tid + 512*q, q=0..3 (full 2048 freqs)
            float v[4], w[4], s0[4], c0[4], s1[4], c1[4], y1[4], y2[4];
#pragma unroll
            for (int q = 0; q < 4; q++) {
                int jp = tid + 512 * q;
                float2 u2 = ((const float2*)g_u)[jp];
                freq_seed(jp, s1[q], c1[q]);
                rotpow_s<12>(s1[q], c1[q], (unsigned)t0, s0[q], c0[q]);
                v[q] = fmaf(u2.x, s0[q],  u2.y * c0[q]);   // us*s + uc*c
                w[q] = fmaf(u2.x, c0[q], -u2.y * s0[q]);   // us*c - uc*s
                y1[q] = 0.f; y2[q] = 0.f;
            }
            __syncthreads();

            // sweep A: amplitude-phase chains; part = sum v
            for (int n = 0; n < nt; n++) {
                sh_part[n * 512 + tid] = (v[0] + v[1]) + (v[2] + v[3]);
#pragma unroll
                for (int q = 0; q < 4; q++) {
                    float nv = fmaf(c1[q], v[q],  s1[q] * w[q]);
                    float nw = fmaf(c1[q], w[q], -s1[q] * v[q]);
                    v[q] = nv; w[q] = nw;
                }
            }
            __syncthreads();
            // reduce rows -> scores -> e (no max subtraction; scores O(10))
            {
                int r = wid;
                if (r < nt) {
                    float vv = 0.f;
#pragma unroll
                    for (int k = 0; k < 16; k++) vv += sh_part[r * 512 + lane + 32 * k];
#pragma unroll
                    for (int o = 16; o; o >>= 1) vv += __shfl_xor_sync(0xffffffffu, vv, o);
                    if (!lane) {
                        int base = r * 8;
                        float es = 0.f;
#pragma unroll
                        for (int p = 0; p < P; p++)
                            es += sh_tab[p * 9 + sh_io[base + p]]
                                + sh_tab[72 + p * 9 + sh_id[base + p]];
                        float sc = fmaf(16.0f, es, vv);
                        sh_e[r] = __expf(sc * (1.0f / 32.0f));
                    }
                }
            }
            __syncthreads();
            // sweep B: Goertzel per q over the chunk's e values
            for (int n = 0; n < nt; n++) {
                float e = sh_e[n];
#pragma unroll
                for (int q = 0; q < 4; q++) {
                    float yn = fmaf(2.f * c1[q], y1[q], e - y2[q]);
                    y2[q] = y1[q]; y1[q] = yn;
                }
            }
            // endgame per q: extract A,B, rotate into absolute phase, scatter
#pragma unroll
            for (int q = 0; q < 4; q++) {
                float sN, cN;
                rotpow_s<4>(s1[q], c1[q], (unsigned)nt, sN, cN);
                float sNm1 = fmaf(sN, c1[q], -cN * s1[q]);
                float cNm1 = fmaf(cN, c1[q],  sN * s1[q]);
                float A = fmaf(sNm1, y1[q], -sN * y2[q]);
                float B = fmaf(cNm1, y1[q], -cN * y2[q]);
                float as = fmaf(s0[q], B,  c0[q] * A);
                float ac = fmaf(c0[q], B, -s0[q] * A);
                int jp = tid + 512 * q;
                atomicAdd(&g_pc[2 * jp],     as);
                atomicAdd(&g_pc[2 * jp + 1], ac);
            }
            // wtab + Z from sh_e
            if (tid < nt * 8) {
                int tt = tid >> 3, p = tid & 7;
                float ww = sh_e[tt];
                atomicAdd(&sh_wt[p * 9 + sh_io[tid]], ww);
                atomicAdd(&sh_wt[72 + p * 9 + sh_id[tid]], ww);
            }
            __syncthreads();
            if (tid < 144) atomicAdd(&g_wtab[tid], sh_wt[tid]);
            if (wid == 0) {
                float z = (lane < nt) ? sh_e[lane] : 0.f;
#pragma unroll
                for (int o = 16; o; o >>= 1) z += __shfl_xor_sync(0xffffffffu, z, o);
                if (!lane) atomicAdd(&g_Z, z);
            }
        }
    }
    gridbar();

    // ===== P5: build c in smem; ov = c @ WV ================================
    if (tid < 144) sh_tab[tid] = g_wtab[tid];
    __syncthreads();
    for (int k = tid; k < DF; k += NTHR) {
        int d = k, p = d >> 9, r = d & 511;
        float a = 0.f;
        if (r < DM) {
#pragma unroll
            for (int e = 0; e < NE; e++) a = fmaf(sh_tab[p * 9 + e], __ldg(&oe[e * DM + r]), a);
        } else {
            int rr = r - DM;
#pragma unroll
            for (int e = 0; e < NE; e++) a = fmaf(sh_tab[72 + p * 9 + e], __ldg(&de[e * DM + rr]), a);
        }
        sh_x[k] = fmaf(16.0f, a, g_pc[d]);
    }
    __syncthreads();
    colmv_sh(WV, sh_x, g_ov, 1024, sh_acc);
    gridbar();

    // ===== P6: oacc = ov @ WO ==============================================
    for (int k = tid; k < DK; k += NTHR) sh_x[k] = g_ov[k];
    __syncthreads();
    colmv_sh(WO, sh_x, g_oacc, 256, sh_acc);
    gridbar();

    // ===== P7: heads =======================================================
    if (bid < 129) {
        const float* Wr; float bias;
        if (bid < 64)       { Wr = Wo + bid * DK;        bias = bo[bid]; }
        else if (bid < 128) { Wr = Wd + (bid - 64) * DK; bias = bd[bid - 64]; }
        else                { Wr = Wv;                   bias = bv[0]; }
        float acc = 0.f;
        if (tid < 256) {
            float4 h4 = ((const float4*)g_oacc)[tid];
            float4 w4 = __ldg(&((const float4*)Wr)[tid]);
            acc = fmaxf(h4.x, 0.f) * w4.x + fmaxf(h4.y, 0.f) * w4.y +
                  fmaxf(h4.z, 0.f) * w4.z + fmaxf(h4.w, 0.f) * w4.w;
        }
#pragma unroll
        for (int o = 16; o; o >>= 1) acc += __shfl_xor_sync(0xffffffffu, acc, o);
        if (!lane && wid < 8) sh_red[wid] = acc;
        __syncthreads();
        if (tid == 0 && bid < out_size) {
            float sum = 0.f;
#pragma unroll
            for (int i = 0; i < 8; i++) sum += sh_red[i];
            out[bid] = sum * (1.0f / g_Z) + bias;
        }
    }
}

// ---------------- host launcher ---------------------------------------------
extern "C" void kernel_launch(void* const* d_in, const int* in_sizes, int n_in,
                              void* d_out, int out_size) {
    const int*   obs = (const int*)d_in[0];
    const float* oe  = (const float*)d_in[1];
    const float* de  = (const float*)d_in[2];
    const float* WQ  = (const float*)d_in[3];
    const float* WK  = (const float*)d_in[4];
    const float* WV  = (const float*)d_in[5];
    const float* WO  = (const float*)d_in[6];
    const float* Wo  = (const float*)d_in[7];
    const float* bo  = (const float*)d_in[8];
    const float* Wd  = (const float*)d_in[9];
    const float* bd  = (const float*)d_in[10];
    const float* Wv  = (const float*)d_in[11];
    const float* bv  = (const float*)d_in[12];
    float* out = (float*)d_out;

    pre_kernel<<<16, 256>>>();
    uber_kernel<<<NBLK, NTHR>>>(obs, oe, de, WQ, WK, WV, WO,
                                Wo, bo, Wd, bd, Wv, bv, out, out_size);
}

// round 15
// speedup vs baseline: 1.2800x; 1.2800x over previous
#include <cuda_runtime.h>
#include <math.h>

#define T      4096
#define P      8
#define DM     256
#define DF     4096
#define DK     1024
#define NE     9

// ---------------- scratch --------------------------------------------------
__device__ float g_x[DF];
__device__ float g_q[DK];
__device__ float g_u[DF];
__device__ float g_fs1[2048], g_fc1[2048];
__device__ float g_wtab[144];
__device__ float g_pc[DF];
__device__ float g_ov[DK];
__device__ float g_oacc[DK];
__device__ float g_Z;

#define LN1E4_OVER_2048 (9.210340371976184 / 2048.0)

// scalar rotpow (branch-free select), B bits: sincos(n*theta) from sincos(theta)
template <int B>
__device__ __forceinline__ void rotpow_s(float ps, float pc, unsigned n,
                                         float& so, float& co) {
    float s = 0.f, c = 1.f;
#pragma unroll
    for (int b = 0; b < B; b++) {
        float ns = fmaf(s, pc, c * ps);
        float nc = fmaf(c, pc, -s * ps);
        bool tk = (n >> b) & 1u;
        s = tk ? ns : s; c = tk ? nc : c;
        float t2 = 2.f * ps * pc;
        pc = fmaf(pc, pc, -ps * ps);
        ps = t2;
    }
    so = s; co = c;
}

// ---------------- K0: zeros + trig tables -----------------------------------
__global__ void k_pre() {
    int g = blockIdx.x * blockDim.x + threadIdx.x;   // 4096 threads
    if (g < 2048) {
        double fij = exp(-(double)g * LN1E4_OVER_2048);
        double ds, dc;
        sincos(fij, &ds, &dc);
        g_fs1[g] = (float)ds; g_fc1[g] = (float)dc;
    }
    if (g < DF) g_pc[g] = 0.f;
    if (g < DK) { g_q[g] = 0.f; g_ov[g] = 0.f; g_oacc[g] = 0.f; }
    if (g < 144) g_wtab[g] = 0.f;
    if (g == 0) g_Z = 0.f;
}

// ---------------- K1: build xlast -------------------------------------------
__global__ void k_xlast(const int* __restrict__ obs,
                        const float* __restrict__ oe,
                        const float* __restrict__ de) {
    int d = blockIdx.x * blockDim.x + threadIdx.x;   // 4096 threads
    int p = d >> 9, r = d & 511;
    int row = 2 * ((T - 1) * P + p) + (r >= DM ? 1 : 0);
    const int* ro = obs + (size_t)row * NE;
    int idx = 0;
#pragma unroll
    for (int e = 0; e < NE; e++) if (ro[e]) idx = e;
    float ev = (r < DM) ? oe[idx * DM + r] : de[idx * DM + (r - DM)];
    int j = d >> 1;
    float s, c;
    rotpow_s<12>(g_fs1[j], g_fc1[j], T - 1, s, c);
    g_x[d] = 16.0f * ev + ((d & 1) ? c : s);
}

// ---------------- one-shot colmv: block = 16 rows, K=1024 -------------------
// y[k] += sum over block's 16 d of x[d]*W[d,k]. 16 LDG.128 in flight/thread.
__global__ void __launch_bounds__(256) k_mv16(const float* __restrict__ W,
                                              const float* __restrict__ x,
                                              float* __restrict__ y) {
    __shared__ float sx[16];
    int tid = threadIdx.x, b = blockIdx.x;
    const float4* W4 = (const float4*)W + (size_t)b * 16 * 256;
    float4 w[16];
#pragma unroll
    for (int i = 0; i < 16; i++) w[i] = __ldg(&W4[i * 256 + tid]);
    if (tid < 16) sx[tid] = __ldg(&x[b * 16 + tid]);
    __syncthreads();
    float4 acc = make_float4(0.f, 0.f, 0.f, 0.f);
#pragma unroll
    for (int i = 0; i < 16; i++) {
        float xv = sx[i];
        acc.x = fmaf(xv, w[i].x, acc.x);
        acc.y = fmaf(xv, w[i].y, acc.y);
        acc.z = fmaf(xv, w[i].z, acc.z);
        acc.w = fmaf(xv, w[i].w, acc.w);
    }
    atomicAdd(&y[4 * tid + 0], acc.x);
    atomicAdd(&y[4 * tid + 1], acc.y);
    atomicAdd(&y[4 * tid + 2], acc.z);
    atomicAdd(&y[4 * tid + 3], acc.w);
}

// ---------------- one-shot colmv with fused c build (WV) --------------------
__global__ void __launch_bounds__(256) k_cmv16(const float* __restrict__ W,
                                               const float* __restrict__ oe,
                                               const float* __restrict__ de,
                                               float* __restrict__ y) {
    __shared__ float sx[16];
    int tid = threadIdx.x, b = blockIdx.x;
    const float4* W4 = (const float4*)W + (size_t)b * 16 * 256;
    float4 w[16];
#pragma unroll
    for (int i = 0; i < 16; i++) w[i] = __ldg(&W4[i * 256 + tid]);
    if (tid < 16) {
        int d = b * 16 + tid;
        int p = d >> 9, r = d & 511;
        float a = 0.f;
        if (r < DM) {
#pragma unroll
            for (int e = 0; e < NE; e++) a = fmaf(g_wtab[p * 9 + e], __ldg(&oe[e * DM + r]), a);
        } else {
            int rr = r - DM;
#pragma unroll
            for (int e = 0; e < NE; e++) a = fmaf(g_wtab[72 + p * 9 + e], __ldg(&de[e * DM + rr]), a);
        }
        sx[tid] = fmaf(16.0f, a, g_pc[d]);
    }
    __syncthreads();
    float4 acc = make_float4(0.f, 0.f, 0.f, 0.f);
#pragma unroll
    for (int i = 0; i < 16; i++) {
        float xv = sx[i];
        acc.x = fmaf(xv, w[i].x, acc.x);
        acc.y = fmaf(xv, w[i].y, acc.y);
        acc.z = fmaf(xv, w[i].z, acc.z);
        acc.w = fmaf(xv, w[i].w, acc.w);
    }
    atomicAdd(&y[4 * tid + 0], acc.x);
    atomicAdd(&y[4 * tid + 1], acc.y);
    atomicAdd(&y[4 * tid + 2], acc.z);
    atomicAdd(&y[4 * tid + 3], acc.w);
}

// ---------------- one-shot rowmv: u = WK @ q (warp per row) -----------------
__global__ void __launch_bounds__(512) k_u(const float* __restrict__ WK) {
    __shared__ float4 sq[256];
    int tid = threadIdx.x, b = blockIdx.x;
    int wid = tid >> 5, lane = tid & 31;
    int row = b * 16 + wid;
    const float4* Wr = (const float4*)(WK + (size_t)row * DK);
    float4 w[8];
#pragma unroll
    for (int i = 0; i < 8; i++) w[i] = __ldg(&Wr[lane + 32 * i]);
    if (tid < 256) sq[tid] = ((const float4*)g_q)[tid];
    __syncthreads();
    float acc = 0.f;
#pragma unroll
    for (int i = 0; i < 8; i++) {
        float4 v = sq[lane + 32 * i];
        acc = fmaf(w[i].x, v.x, acc);
        acc = fmaf(w[i].y, v.y, acc);
        acc = fmaf(w[i].z, v.z, acc);
        acc = fmaf(w[i].w, v.w, acc);
    }
#pragma unroll
    for (int o = 16; o; o >>= 1) acc += __shfl_xor_sync(0xffffffffu, acc, o);
    if (!lane) g_u[row] = acc;
}

// ---------------- K4: fused scores + e + wtab + Z + pc (R13 P34) ------------
__global__ void __launch_bounds__(512) k_p34(const int* __restrict__ obs,
                                             const float* __restrict__ oe,
                                             const float* __restrict__ de) {
    __shared__ float sh_part[14 * 512];   // 28KB
    __shared__ float sh_tab[144];
    __shared__ float sh_wt[144];
    __shared__ float sh_e[32];
    __shared__ int   sh_io[224], sh_id[224];

    int tid = threadIdx.x, bid = blockIdx.x;
    int wid = tid >> 5, lane = tid & 31;

    int t0 = bid * 28;
    int nt = min(28, T - t0);
    if (nt <= 0) return;

    // local io/id decode
    if (tid < nt * 8) {
        int tt = tid >> 3, p = tid & 7;
        int t = t0 + tt;
        const int* r0 = obs + (size_t)(2 * (t * P + p)) * NE;
        int io = 0, id = 0;
#pragma unroll
        for (int e = 0; e < NE; e++) {
            if (r0[e])      io = e;
            if (r0[NE + e]) id = e;
        }
        sh_io[tid] = io;
        sh_id[tid] = id;
    }
    // utab
    for (int ent = wid; ent < 144; ent += 16) {
        int kind = ent / 72, p = (ent % 72) / 9, e = ent % 9;
        const float4* e4 = (const float4*)((kind ? de : oe) + e * DM);
        const float4* u4 = (const float4*)(g_u + p * 512 + kind * DM);
        float acc = 0.f;
#pragma unroll
        for (int i = 0; i < 2; i++) {
            float4 a = __ldg(&e4[lane + 32 * i]);
            float4 b = u4[lane + 32 * i];
            acc += a.x * b.x + a.y * b.y + a.z * b.z + a.w * b.w;
        }
#pragma unroll
        for (int o = 16; o; o >>= 1) acc += __shfl_xor_sync(0xffffffffu, acc, o);
        if (!lane) sh_tab[ent] = acc;
    }
    if (tid < 144) sh_wt[tid] = 0.f;

    // seeds: jp = tid + 512*q
    float v[4], w[4], s0[4], c0[4], s1[4], c1[4], y1[4], y2[4];
    float as[4] = {0.f, 0.f, 0.f, 0.f}, ac[4] = {0.f, 0.f, 0.f, 0.f};
#pragma unroll
    for (int q = 0; q < 4; q++) {
        int jp = tid + 512 * q;
        float2 u2 = ((const float2*)g_u)[jp];
        s1[q] = g_fs1[jp]; c1[q] = g_fc1[jp];
        rotpow_s<12>(s1[q], c1[q], (unsigned)t0, s0[q], c0[q]);
        v[q] = fmaf(u2.x, s0[q],  u2.y * c0[q]);
        w[q] = fmaf(u2.x, c0[q], -u2.y * s0[q]);
        y1[q] = 0.f; y2[q] = 0.f;
    }
    __syncthreads();

    for (int sub = 0; sub < 28; sub += 14) {
        int cnt = min(14, nt - sub);
        if (cnt <= 0) break;
        // sweep A
        for (int n = 0; n < cnt; n++) {
            sh_part[n * 512 + tid] = (v[0] + v[1]) + (v[2] + v[3]);
#pragma unroll
            for (int q = 0; q < 4; q++) {
                float nv = fmaf(c1[q], v[q],  s1[q] * w[q]);
                float nw = fmaf(c1[q], w[q], -s1[q] * v[q]);
                v[q] = nv; w[q] = nw;
            }
        }
        __syncthreads();
        // reduce -> scores -> e
        {
            int r = wid;
            if (r < cnt) {
                float vv = 0.f;
#pragma unroll
                for (int k = 0; k < 16; k++) vv += sh_part[r * 512 + lane + 32 * k];
#pragma unroll
                for (int o = 16; o; o >>= 1) vv += __shfl_xor_sync(0xffffffffu, vv, o);
                if (!lane) {
                    int base = (sub + r) * 8;
                    float es = 0.f;
#pragma unroll
                    for (int p = 0; p < P; p++)
                        es += sh_tab[p * 9 + sh_io[base + p]]
                            + sh_tab[72 + p * 9 + sh_id[base + p]];
                    float sc = fmaf(16.0f, es, vv);
                    sh_e[sub + r] = __expf(sc * (1.0f / 32.0f));
                }
            }
        }
        __syncthreads();
        // sweep B: Goertzel
        for (int n = 0; n < cnt; n++) {
            float e = sh_e[sub + n];
#pragma unroll
            for (int q = 0; q < 4; q++) {
                float yn = fmaf(2.f * c1[q], y1[q], e - y2[q]);
                y2[q] = y1[q]; y1[q] = yn;
            }
        }
#pragma unroll
        for (int q = 0; q < 4; q++) {
            float sN, cN;
            rotpow_s<4>(s1[q], c1[q], (unsigned)cnt, sN, cN);
            float sNm1 = fmaf(sN, c1[q], -cN * s1[q]);
            float cNm1 = fmaf(cN, c1[q],  sN * s1[q]);
            float A = fmaf(sNm1, y1[q], -sN * y2[q]);
            float B = fmaf(cNm1, y1[q], -cN * y2[q]);
            as[q] += fmaf(s0[q], B,  c0[q] * A);
            ac[q] += fmaf(c0[q], B, -s0[q] * A);
            float ns0 = fmaf(s0[q], cN,  c0[q] * sN);
            float nc0 = fmaf(c0[q], cN, -s0[q] * sN);
            s0[q] = ns0; c0[q] = nc0;
            y1[q] = 0.f; y2[q] = 0.f;
        }
    }
    // pc scatter
#pragma unroll
    for (int q = 0; q < 4; q++) {
        int jp = tid + 512 * q;
        atomicAdd(&g_pc[2 * jp],     as[q]);
        atomicAdd(&g_pc[2 * jp + 1], ac[q]);
    }
    // wtab + Z
    if (tid < nt * 8) {
        int tt = tid >> 3, p = tid & 7;
        float ww = sh_e[tt];
        atomicAdd(&sh_wt[p * 9 + sh_io[tid]], ww);
        atomicAdd(&sh_wt[72 + p * 9 + sh_id[tid]], ww);
    }
    __syncthreads();
    if (tid < 144) atomicAdd(&g_wtab[tid], sh_wt[tid]);
    if (wid == 0) {
        float z = (lane < nt) ? sh_e[lane] : 0.f;
#pragma unroll
        for (int o = 16; o; o >>= 1) z += __shfl_xor_sync(0xffffffffu, z, o);
        if (!lane) atomicAdd(&g_Z, z);
    }
}

// ---------------- K7: heads -------------------------------------------------
__global__ void __launch_bounds__(128) k_heads(const float* __restrict__ Wo,
                                               const float* __restrict__ bo,
                                               const float* __restrict__ Wd,
                                               const float* __restrict__ bd,
                                               const float* __restrict__ Wv,
                                               const float* __restrict__ bv,
                                               float* __restrict__ out, int out_size) {
    int o = blockIdx.x;                  // 129 blocks
    const float* Wr; float bias;
    if (o < 64)       { Wr = Wo + o * DK;        bias = bo[o]; }
    else if (o < 128) { Wr = Wd + (o - 64) * DK; bias = bd[o - 64]; }
    else              { Wr = Wv;                 bias = bv[0]; }
    int tid = threadIdx.x;
    float4 h4 = ((const float4*)g_oacc)[tid * 2];
    float4 h5 = ((const float4*)g_oacc)[tid * 2 + 1];
    float4 w4 = __ldg(&((const float4*)Wr)[tid * 2]);
    float4 w5 = __ldg(&((const float4*)Wr)[tid * 2 + 1]);
    float acc = fmaxf(h4.x, 0.f) * w4.x + fmaxf(h4.y, 0.f) * w4.y +
                fmaxf(h4.z, 0.f) * w4.z + fmaxf(h4.w, 0.f) * w4.w +
                fmaxf(h5.x, 0.f) * w5.x + fmaxf(h5.y, 0.f) * w5.y +
                fmaxf(h5.z, 0.f) * w5.z + fmaxf(h5.w, 0.f) * w5.w;
#pragma unroll
    for (int off = 16; off; off >>= 1) acc += __shfl_xor_sync(0xffffffffu, acc, off);
    __shared__ float sred[4];
    int lane = tid & 31, wid = tid >> 5;
    if (!lane) sred[wid] = acc;
    __syncthreads();
    if (tid == 0 && o < out_size)
        out[o] = (sred[0] + sred[1] + sred[2] + sred[3]) * (1.0f / g_Z) + bias;
}

// ---------------- host launcher ---------------------------------------------
extern "C" void kernel_launch(void* const* d_in, const int* in_sizes, int n_in,
                              void* d_out, int out_size) {
    const int*   obs = (const int*)d_in[0];
    const float* oe  = (const float*)d_in[1];
    const float* de  = (const float*)d_in[2];
    const float* WQ  = (const float*)d_in[3];
    const float* WK  = (const float*)d_in[4];
    const float* WV  = (const float*)d_in[5];
    const float* WO  = (const float*)d_in[6];
    const float* Wo  = (const float*)d_in[7];
    const float* bo  = (const float*)d_in[8];
    const float* Wd  = (const float*)d_in[9];
    const float* bd  = (const float*)d_in[10];
    const float* Wv  = (const float*)d_in[11];
    const float* bv  = (const float*)d_in[12];
    float* out = (float*)d_out;

    float *p_x, *p_q, *p_ov, *p_oacc;
    cudaGetSymbolAddress((void**)&p_x, g_x);
    cudaGetSymbolAddress((void**)&p_q, g_q);
    cudaGetSymbolAddress((void**)&p_ov, g_ov);
    cudaGetSymbolAddress((void**)&p_oacc, g_oacc);

    k_pre<<<16, 256>>>();
    k_xlast<<<16, 256>>>(obs, oe, de);
    k_mv16<<<256, 256>>>(WQ, p_x, p_q);        // q = x @ WQ
    k_u<<<256, 512>>>(WK);                      // u = WK @ q
    k_p34<<<147, 512>>>(obs, oe, de);           // scores/e/wtab/Z/pc (147*28 >= 4096)
    k_cmv16<<<256, 256>>>(WV, oe, de, p_ov);    // c build + ov = c @ WV
    k_mv16<<<64, 256>>>(WO, p_ov, p_oacc);      // oacc = ov @ WO
    k_heads<<<129, 128>>>(Wo, bo, Wd, bd, Wv, bv, out, out_size);
}

// round 16
// speedup vs baseline: 1.5741x; 1.2298x over previous
#include <cuda_runtime.h>
#include <math.h>

#define T      4096
#define P      8
#define DM     256
#define DF     4096
#define DK     1024
#define NE     9

// ---------------- scratch --------------------------------------------------
__device__ float g_q[DK];
__device__ float g_u[DF];
__device__ float g_fs1[2048], g_fc1[2048];
__device__ float g_wtab[144];
__device__ float g_pc[DF];
__device__ float g_ov[DK];
__device__ float g_oacc[DK];
__device__ float g_Z;

#define LN1E4_OVER_2048 (9.210340371976184 / 2048.0)

// scalar rotpow (branch-free select), B bits: sincos(n*theta) from sincos(theta)
template <int B>
__device__ __forceinline__ void rotpow_s(float ps, float pc, unsigned n,
                                         float& so, float& co) {
    float s = 0.f, c = 1.f;
#pragma unroll
    for (int b = 0; b < B; b++) {
        float ns = fmaf(s, pc, c * ps);
        float nc = fmaf(c, pc, -s * ps);
        bool tk = (n >> b) & 1u;
        s = tk ? ns : s; c = tk ? nc : c;
        float t2 = 2.f * ps * pc;
        pc = fmaf(pc, pc, -ps * ps);
        ps = t2;
    }
    so = s; co = c;
}

// ---------------- K0: zeros + trig tables -----------------------------------
__global__ void k_pre() {
    int g = blockIdx.x * blockDim.x + threadIdx.x;   // 4096 threads
    if (g < 2048) {
        double fij = exp(-(double)g * LN1E4_OVER_2048);
        double ds, dc;
        sincos(fij, &ds, &dc);
        g_fs1[g] = (float)ds; g_fc1[g] = (float)dc;
    }
    if (g < DF) g_pc[g] = 0.f;
    if (g < DK) { g_q[g] = 0.f; g_ov[g] = 0.f; g_oacc[g] = 0.f; }
    if (g < 144) g_wtab[g] = 0.f;
    if (g == 0) g_Z = 0.f;
}

// ---------------- shared colmv core: 32 rows, two 256-halves ----------------
// sx[32] must be filled by caller section; W base = block's 32 rows.
__device__ __forceinline__ void mv32_core(const float4* __restrict__ W4,
                                          const float* sx, float* sacc,
                                          float* __restrict__ y,
                                          int htid, int half) {
    float4 w[16];
#pragma unroll
    for (int i = 0; i < 16; i++)
        w[i] = __ldg(&W4[(size_t)(half * 16 + i) * 256 + htid]);
    __syncthreads();                    // sx ready
    float4 acc = make_float4(0.f, 0.f, 0.f, 0.f);
#pragma unroll
    for (int i = 0; i < 16; i++) {
        float xv = sx[half * 16 + i];
        acc.x = fmaf(xv, w[i].x, acc.x);
        acc.y = fmaf(xv, w[i].y, acc.y);
        acc.z = fmaf(xv, w[i].z, acc.z);
        acc.w = fmaf(xv, w[i].w, acc.w);
    }
    if (half == 1) ((float4*)sacc)[htid] = acc;
    __syncthreads();
    if (half == 0) {
        float4 o = ((float4*)sacc)[htid];
        atomicAdd(&y[4 * htid + 0], acc.x + o.x);
        atomicAdd(&y[4 * htid + 1], acc.y + o.y);
        atomicAdd(&y[4 * htid + 2], acc.z + o.z);
        atomicAdd(&y[4 * htid + 3], acc.w + o.w);
    }
}

// ---------------- K1: q = x @ WQ, x built in-block (32 d per block) ---------
__global__ void __launch_bounds__(512) k_qmv(const int* __restrict__ obs,
                                             const float* __restrict__ oe,
                                             const float* __restrict__ de,
                                             const float* __restrict__ WQ) {
    __shared__ float sx[32];
    __shared__ float sacc[DK];
    int tid = threadIdx.x, b = blockIdx.x;       // 128 blocks
    int htid = tid & 255, half = tid >> 8;
    if (tid < 32) {
        int d = b * 32 + tid;
        int p = d >> 9, r = d & 511;
        int row = 2 * ((T - 1) * P + p) + (r >= DM ? 1 : 0);
        const int* ro = obs + (size_t)row * NE;
        int idx = 0;
#pragma unroll
        for (int e = 0; e < NE; e++) if (ro[e]) idx = e;
        float ev = (r < DM) ? oe[idx * DM + r] : de[idx * DM + (r - DM)];
        int j = d >> 1;
        float fij = expf(-(float)j * (float)LN1E4_OVER_2048);
        float s1, c1; sincosf(fij, &s1, &c1);
        float s, c; rotpow_s<12>(s1, c1, T - 1, s, c);
        sx[tid] = 16.0f * ev + ((d & 1) ? c : s);
    }
    mv32_core((const float4*)WQ + (size_t)b * 32 * 256, sx, sacc, g_q, htid, half);
}

// ---------------- K5: ov = c @ WV, c built in-block -------------------------
__global__ void __launch_bounds__(512) k_cmv(const float* __restrict__ oe,
                                             const float* __restrict__ de,
                                             const float* __restrict__ WV) {
    __shared__ float sx[32];
    __shared__ float sacc[DK];
    int tid = threadIdx.x, b = blockIdx.x;       // 128 blocks
    int htid = tid & 255, half = tid >> 8;
    if (tid < 32) {
        int d = b * 32 + tid;
        int p = d >> 9, r = d & 511;
        float a = 0.f;
        if (r < DM) {
#pragma unroll
            for (int e = 0; e < NE; e++) a = fmaf(g_wtab[p * 9 + e], __ldg(&oe[e * DM + r]), a);
        } else {
            int rr = r - DM;
#pragma unroll
            for (int e = 0; e < NE; e++) a = fmaf(g_wtab[72 + p * 9 + e], __ldg(&de[e * DM + rr]), a);
        }
        sx[tid] = fmaf(16.0f, a, g_pc[d]);
    }
    mv32_core((const float4*)WV + (size_t)b * 32 * 256, sx, sacc, g_ov, htid, half);
}

// ---------------- K6: oacc = ov @ WO (32 blocks x 32 rows) ------------------
__global__ void __launch_bounds__(512) k_omv(const float* __restrict__ WO) {
    __shared__ float sx[32];
    __shared__ float sacc[DK];
    int tid = threadIdx.x, b = blockIdx.x;       // 32 blocks
    int htid = tid & 255, half = tid >> 8;
    if (tid < 32) sx[tid] = g_ov[b * 32 + tid];
    mv32_core((const float4*)WO + (size_t)b * 32 * 256, sx, sacc, g_oacc, htid, half);
}

// ---------------- K2: u = WK @ q (warp per 2 rows, 128 blocks) --------------
__global__ void __launch_bounds__(512) k_u(const float* __restrict__ WK) {
    __shared__ float4 sq[256];
    int tid = threadIdx.x, b = blockIdx.x;       // 128 blocks
    int wid = tid >> 5, lane = tid & 31;
    int r0 = b * 32 + wid * 2;
    const float4* Wa = (const float4*)(WK + (size_t)r0 * DK);
    const float4* Wb = (const float4*)(WK + (size_t)(r0 + 1) * DK);
    float4 wa[8], wb[8];
#pragma unroll
    for (int i = 0; i < 8; i++) wa[i] = __ldg(&Wa[lane + 32 * i]);
#pragma unroll
    for (int i = 0; i < 8; i++) wb[i] = __ldg(&Wb[lane + 32 * i]);
    if (tid < 256) sq[tid] = ((const float4*)g_q)[tid];
    __syncthreads();
    float accA = 0.f, accB = 0.f;
#pragma unroll
    for (int i = 0; i < 8; i++) {
        float4 v = sq[lane + 32 * i];
        accA = fmaf(wa[i].x, v.x, accA); accA = fmaf(wa[i].y, v.y, accA);
        accA = fmaf(wa[i].z, v.z, accA); accA = fmaf(wa[i].w, v.w, accA);
        accB = fmaf(wb[i].x, v.x, accB); accB = fmaf(wb[i].y, v.y, accB);
        accB = fmaf(wb[i].z, v.z, accB); accB = fmaf(wb[i].w, v.w, accB);
    }
#pragma unroll
    for (int o = 16; o; o >>= 1) {
        accA += __shfl_xor_sync(0xffffffffu, accA, o);
        accB += __shfl_xor_sync(0xffffffffu, accB, o);
    }
    if (!lane) { g_u[r0] = accA; g_u[r0 + 1] = accB; }
}

// ---------------- K4: fused scores + e + wtab + Z + pc ----------------------
__global__ void __launch_bounds__(512) k_p34(const int* __restrict__ obs,
                                             const float* __restrict__ oe,
                                             const float* __restrict__ de) {
    __shared__ float sh_part[14 * 512];   // 28KB
    __shared__ float sh_tab[144];
    __shared__ float sh_wt[144];
    __shared__ float sh_e[32];
    __shared__ int   sh_io[224], sh_id[224];

    int tid = threadIdx.x, bid = blockIdx.x;
    int wid = tid >> 5, lane = tid & 31;

    int t0 = bid * 28;
    int nt = min(28, T - t0);
    if (nt <= 0) return;

    if (tid < nt * 8) {
        int tt = tid >> 3, p = tid & 7;
        int t = t0 + tt;
        const int* r0 = obs + (size_t)(2 * (t * P + p)) * NE;
        int io = 0, id = 0;
#pragma unroll
        for (int e = 0; e < NE; e++) {
            if (r0[e])      io = e;
            if (r0[NE + e]) id = e;
        }
        sh_io[tid] = io;
        sh_id[tid] = id;
    }
    for (int ent = wid; ent < 144; ent += 16) {
        int kind = ent / 72, p = (ent % 72) / 9, e = ent % 9;
        const float4* e4 = (const float4*)((kind ? de : oe) + e * DM);
        const float4* u4 = (const float4*)(g_u + p * 512 + kind * DM);
        float acc = 0.f;
#pragma unroll
        for (int i = 0; i < 2; i++) {
            float4 a = __ldg(&e4[lane + 32 * i]);
            float4 b = u4[lane + 32 * i];
            acc += a.x * b.x + a.y * b.y + a.z * b.z + a.w * b.w;
        }
#pragma unroll
        for (int o = 16; o; o >>= 1) acc += __shfl_xor_sync(0xffffffffu, acc, o);
        if (!lane) sh_tab[ent] = acc;
    }
    if (tid < 144) sh_wt[tid] = 0.f;

    float v[4], w[4], s0[4], c0[4], s1[4], c1[4], y1[4], y2[4];
    float as[4] = {0.f, 0.f, 0.f, 0.f}, ac[4] = {0.f, 0.f, 0.f, 0.f};
#pragma unroll
    for (int q = 0; q < 4; q++) {
        int jp = tid + 512 * q;
        float2 u2 = ((const float2*)g_u)[jp];
        s1[q] = g_fs1[jp]; c1[q] = g_fc1[jp];
        rotpow_s<12>(s1[q], c1[q], (unsigned)t0, s0[q], c0[q]);
        v[q] = fmaf(u2.x, s0[q],  u2.y * c0[q]);
        w[q] = fmaf(u2.x, c0[q], -u2.y * s0[q]);
        y1[q] = 0.f; y2[q] = 0.f;
    }
    __syncthreads();

    for (int sub = 0; sub < 28; sub += 14) {
        int cnt = min(14, nt - sub);
        if (cnt <= 0) break;
        for (int n = 0; n < cnt; n++) {
            sh_part[n * 512 + tid] = (v[0] + v[1]) + (v[2] + v[3]);
#pragma unroll
            for (int q = 0; q < 4; q++) {
                float nv = fmaf(c1[q], v[q],  s1[q] * w[q]);
                float nw = fmaf(c1[q], w[q], -s1[q] * v[q]);
                v[q] = nv; w[q] = nw;
            }
        }
        __syncthreads();
        {
            int r = wid;
            if (r < cnt) {
                float vv = 0.f;
#pragma unroll
                for (int k = 0; k < 16; k++) vv += sh_part[r * 512 + lane + 32 * k];
#pragma unroll
                for (int o = 16; o; o >>= 1) vv += __shfl_xor_sync(0xffffffffu, vv, o);
                if (!lane) {
                    int base = (sub + r) * 8;
                    float es = 0.f;
#pragma unroll
                    for (int p = 0; p < P; p++)
                        es += sh_tab[p * 9 + sh_io[base + p]]
                            + sh_tab[72 + p * 9 + sh_id[base + p]];
                    float sc = fmaf(16.0f, es, vv);
                    sh_e[sub + r] = __expf(sc * (1.0f / 32.0f));
                }
            }
        }
        __syncthreads();
        for (int n = 0; n < cnt; n++) {
            float e = sh_e[sub + n];
#pragma unroll
            for (int q = 0; q < 4; q++) {
                float yn = fmaf(2.f * c1[q], y1[q], e - y2[q]);
                y2[q] = y1[q]; y1[q] = yn;
            }
        }
#pragma unroll
        for (int q = 0; q < 4; q++) {
            float sN, cN;
            rotpow_s<4>(s1[q], c1[q], (unsigned)cnt, sN, cN);
            float sNm1 = fmaf(sN, c1[q], -cN * s1[q]);
            float cNm1 = fmaf(cN, c1[q],  sN * s1[q]);
            float A = fmaf(sNm1, y1[q], -sN * y2[q]);
            float B = fmaf(cNm1, y1[q], -cN * y2[q]);
            as[q] += fmaf(s0[q], B,  c0[q] * A);
            ac[q] += fmaf(c0[q], B, -s0[q] * A);
            float ns0 = fmaf(s0[q], cN,  c0[q] * sN);
            float nc0 = fmaf(c0[q], cN, -s0[q] * sN);
            s0[q] = ns0; c0[q] = nc0;
            y1[q] = 0.f; y2[q] = 0.f;
        }
    }
#pragma unroll
    for (int q = 0; q < 4; q++) {
        int jp = tid + 512 * q;
        atomicAdd(&g_pc[2 * jp],     as[q]);
        atomicAdd(&g_pc[2 * jp + 1], ac[q]);
    }
    if (tid < nt * 8) {
        int tt = tid >> 3, p = tid & 7;
        float ww = sh_e[tt];
        atomicAdd(&sh_wt[p * 9 + sh_io[tid]], ww);
        atomicAdd(&sh_wt[72 + p * 9 + sh_id[tid]], ww);
    }
    __syncthreads();
    if (tid < 144) atomicAdd(&g_wtab[tid], sh_wt[tid]);
    if (wid == 0) {
        float z = (lane < nt) ? sh_e[lane] : 0.f;
#pragma unroll
        for (int o = 16; o; o >>= 1) z += __shfl_xor_sync(0xffffffffu, z, o);
        if (!lane) atomicAdd(&g_Z, z);
    }
}

// ---------------- K7: heads -------------------------------------------------
__global__ void __launch_bounds__(128) k_heads(const float* __restrict__ Wo,
                                               const float* __restrict__ bo,
                                               const float* __restrict__ Wd,
                                               const float* __restrict__ bd,
                                               const float* __restrict__ Wv,
                                               const float* __restrict__ bv,
                                               float* __restrict__ out, int out_size) {
    int o = blockIdx.x;                  // 129 blocks
    const float* Wr; float bias;
    if (o < 64)       { Wr = Wo + o * DK;        bias = bo[o]; }
    else if (o < 128) { Wr = Wd + (o - 64) * DK; bias = bd[o - 64]; }
    else              { Wr = Wv;                 bias = bv[0]; }
    int tid = threadIdx.x;
    float4 h4 = ((const float4*)g_oacc)[tid * 2];
    float4 h5 = ((const float4*)g_oacc)[tid * 2 + 1];
    float4 w4 = __ldg(&((const float4*)Wr)[tid * 2]);
    float4 w5 = __ldg(&((const float4*)Wr)[tid * 2 + 1]);
    float acc = fmaxf(h4.x, 0.f) * w4.x + fmaxf(h4.y, 0.f) * w4.y +
                fmaxf(h4.z, 0.f) * w4.z + fmaxf(h4.w, 0.f) * w4.w +
                fmaxf(h5.x, 0.f) * w5.x + fmaxf(h5.y, 0.f) * w5.y +
                fmaxf(h5.z, 0.f) * w5.z + fmaxf(h5.w, 0.f) * w5.w;
#pragma unroll
    for (int off = 16; off; off >>= 1) acc += __shfl_xor_sync(0xffffffffu, acc, off);
    __shared__ float sred[4];
    int lane = tid & 31, wid = tid >> 5;
    if (!lane) sred[wid] = acc;
    __syncthreads();
    if (tid == 0 && o < out_size)
        out[o] = (sred[0] + sred[1] + sred[2] + sred[3]) * (1.0f / g_Z) + bias;
}

// ---------------- host launcher ---------------------------------------------
extern "C" void kernel_launch(void* const* d_in, const int* in_sizes, int n_in,
                              void* d_out, int out_size) {
    const int*   obs = (const int*)d_in[0];
    const float* oe  = (const float*)d_in[1];
    const float* de  = (const float*)d_in[2];
    const float* WQ  = (const float*)d_in[3];
    const float* WK  = (const float*)d_in[4];
    const float* WV  = (const float*)d_in[5];
    const float* WO  = (const float*)d_in[6];
    const float* Wo  = (const float*)d_in[7];
    const float* bo  = (const float*)d_in[8];
    const float* Wd  = (const float*)d_in[9];
    const float* bd  = (const float*)d_in[10];
    const float* Wv  = (const float*)d_in[11];
    const float* bv  = (const float*)d_in[12];
    float* out = (float*)d_out;

    k_pre<<<16, 256>>>();
    k_qmv<<<128, 512>>>(obs, oe, de, WQ);       // x build + q = x @ WQ
    k_u<<<128, 512>>>(WK);                       // u = WK @ q
    k_p34<<<147, 512>>>(obs, oe, de);            // scores/e/wtab/Z/pc
    k_cmv<<<128, 512>>>(oe, de, WV);             // c build + ov = c @ WV
    k_omv<<<32, 512>>>(WO);                      // oacc = ov @ WO
    k_heads<<<129, 128>>>(Wo, bo, Wd, bd, Wv, bv, out, out_size);
}